// round 14
// baseline (speedup 1.0000x reference)
#include <cuda_runtime.h>
#include <cuda_fp16.h>
#include <cstdint>

typedef unsigned long long ull;

#define BATCH   2048
#define TSTEPS  250
#define DIN     128
#define HID     100
#define G4      400
#define MTOT    (BATCH*TSTEPS)

// Scratch for xz : GATE-INTERLEAVED layout [m][j][g]  (index = m*400 + j*4 + g)
__device__ float g_xz[(size_t)MTOT * G4];
// Pre-split Wi (written once per launch by wi_split_kernel)
__device__ uint32_t g_wi_hi[64 * G4];
__device__ uint32_t g_wi_lo[64 * G4];

// ---------------------------------------------------------------------------
// helpers
// ---------------------------------------------------------------------------
__device__ __forceinline__ uint32_t sptr(const void* p) {
    return (uint32_t)__cvta_generic_to_shared(p);
}
__device__ __forceinline__ void cpasync16(uint32_t dst, const void* src) {
    asm volatile("cp.async.ca.shared.global [%0], [%1], 16;" :: "r"(dst), "l"(src));
}
__device__ __forceinline__ void mma_f16(float c[4], uint32_t a0, uint32_t a1,
                                        uint32_t a2, uint32_t a3,
                                        uint32_t b0, uint32_t b1) {
    asm volatile(
        "mma.sync.aligned.m16n8k16.row.col.f32.f16.f16.f32 "
        "{%0,%1,%2,%3}, {%4,%5,%6,%7}, {%8,%9}, {%0,%1,%2,%3};"
        : "+f"(c[0]), "+f"(c[1]), "+f"(c[2]), "+f"(c[3])
        : "r"(a0), "r"(a1), "r"(a2), "r"(a3), "r"(b0), "r"(b1));
}
__device__ __forceinline__ void mma_f16_k8(float c[4], uint32_t a0, uint32_t a1,
                                           uint32_t b0) {
    asm volatile(
        "mma.sync.aligned.m16n8k8.row.col.f32.f16.f16.f32 "
        "{%0,%1,%2,%3}, {%4,%5}, {%6}, {%0,%1,%2,%3};"
        : "+f"(c[0]), "+f"(c[1]), "+f"(c[2]), "+f"(c[3])
        : "r"(a0), "r"(a1), "r"(b0));
}
__device__ __forceinline__ void ldmx4(uint32_t& r0, uint32_t& r1,
                                      uint32_t& r2, uint32_t& r3, uint32_t a) {
    asm volatile("ldmatrix.sync.aligned.m8n8.x4.shared.b16 {%0,%1,%2,%3}, [%4];"
        : "=r"(r0), "=r"(r1), "=r"(r2), "=r"(r3) : "r"(a));
}
__device__ __forceinline__ void ldmx2(uint32_t& r0, uint32_t& r1, uint32_t a) {
    asm volatile("ldmatrix.sync.aligned.m8n8.x2.shared.b16 {%0,%1}, [%2];"
        : "=r"(r0), "=r"(r1) : "r"(a));
}

// ---------------------------------------------------------------------------
// Kernel 0: pre-split Wi into hi/lo f16x2 k-pair layout (once per launch).
// ---------------------------------------------------------------------------
__global__ __launch_bounds__(256) void wi_split_kernel(
    const float* __restrict__ Wi)
{
    int i = blockIdx.x * 256 + threadIdx.x;
    if (i >= 64 * G4) return;
    int kp = i / G4, c = i - kp * G4;
    float f0 = Wi[(size_t)(2 * kp) * G4 + c];
    float f1 = Wi[(size_t)(2 * kp + 1) * G4 + c];
    __half2 h = __floats2half2_rn(f0, f1);
    float2 hf = __half22float2(h);
    __half2 l = __floats2half2_rn((f0 - hf.x) * 2048.f,
                                  (f1 - hf.y) * 2048.f);
    g_wi_hi[i] = *(uint32_t*)&h;
    g_wi_lo[i] = *(uint32_t*)&l;
}

// ---------------------------------------------------------------------------
// Kernel 1: xz = x@Wi + bh via fp16 split-3 mma.sync.
// RESTRUCTURED (R13): grid = 8000 m-tiles only; each CTA loads its x tile
// ONCE and loops over the 5 n-blocks with double-buffered cp.async B
// prefetch (from pre-split g_wi_*). Per-element MMA math identical to R12.
// ---------------------------------------------------------------------------
#define BM 64
#define A_STR 68
#define B_STR 104
#define SO_STR 84
// smem layout (u32): A hi/lo, 2 B buffers (hi+lo each), bias[400]
#define G_OFF_AHI 0
#define G_OFF_ALO (64 * A_STR)
#define G_OFF_B   (2 * 64 * A_STR)                  // 8704
#define G_BBUF_U32 (2 * 64 * B_STR)                 // 13312 per buffer (hi+lo)
#define G_OFF_BIAS (G_OFF_B + 2 * G_BBUF_U32)       // 35328
#define G_SMEM_BYTES ((G_OFF_BIAS + 400) * 4)       // 142,912 B

__global__ __launch_bounds__(128) void gemm_xz_kernel(
    const float* __restrict__ x,
    const float* __restrict__ bh)
{
    extern __shared__ uint32_t smg[];
    uint32_t* a_hi = smg + G_OFF_AHI;
    uint32_t* a_lo = smg + G_OFF_ALO;
    float*    sbh  = (float*)(smg + G_OFF_BIAS);    // [5][80] staged order

    const int tid = threadIdx.x;
    const int m0  = blockIdx.x * BM;

    // bias, staged order per n-block: sbh[nb*80 + jj*4+gg] = bh[gg*100+nb*20+jj]
    for (int i = tid; i < 400; i += 128) {
        int nb = i / 80, rem = i % 80;
        int jj = rem >> 2, gg = rem & 3;
        sbh[i] = bh[gg * 100 + nb * 20 + jj];
    }

    // prefetch B block 0 into buffer 0 (group G0)
    {
        uint32_t* buf = smg + G_OFF_B;
        const uint32_t bhs = sptr(buf);
        const uint32_t bls = sptr(buf + 64 * B_STR);
#pragma unroll
        for (int q = 0; q < 10; q++) {
            int idx = tid + q * 128;
            int kp = idx / 20, rem = idx % 20;
            int g = rem / 5, cc = rem % 5;
            int soff = kp * G4 + g * 100 + 0 * 20 + cc * 4;
            int doff = (kp * B_STR + g * 20 + cc * 4) * 4;
            cpasync16(bhs + doff, g_wi_hi + soff);
            cpasync16(bls + doff, g_wi_lo + soff);
        }
        asm volatile("cp.async.commit_group;");
    }

    // x tile: 64 rows x 64 k-pairs, split hi/lo (overlaps B0 prefetch)
#pragma unroll
    for (int q = 0; q < 32; q++) {
        int idx = tid + q * 128;
        int r = idx >> 6, kp = idx & 63;
        float2 v = *(const float2*)(x + (size_t)(m0 + r) * DIN + 2 * kp);
        __half2 h = __floats2half2_rn(v.x, v.y);
        float2 hf = __half22float2(h);
        __half2 l = __floats2half2_rn((v.x - hf.x) * 2048.f,
                                      (v.y - hf.y) * 2048.f);
        a_hi[r * A_STR + kp] = *(uint32_t*)&h;
        a_lo[r * A_STR + kp] = *(uint32_t*)&l;
    }

    const int warp = tid >> 5, lane = tid & 31;
    const int gid = lane >> 2, tig = lane & 3;
    const int r0w = warp * 16;

    const uint32_t* ah_r0 = a_hi + (r0w + gid) * A_STR;
    const uint32_t* ah_r1 = a_hi + (r0w + gid + 8) * A_STR;
    const uint32_t* al_r0 = a_lo + (r0w + gid) * A_STR;
    const uint32_t* al_r1 = a_lo + (r0w + gid + 8) * A_STR;

    for (int nb = 0; nb < 5; nb++) {
        uint32_t* bufc = smg + G_OFF_B + (nb & 1) * G_BBUF_U32;

        // prefetch next n-block into the other buffer
        if (nb + 1 < 5) {
            uint32_t* bufn = smg + G_OFF_B + ((nb + 1) & 1) * G_BBUF_U32;
            const uint32_t bhs = sptr(bufn);
            const uint32_t bls = sptr(bufn + 64 * B_STR);
#pragma unroll
            for (int q = 0; q < 10; q++) {
                int idx = tid + q * 128;
                int kp = idx / 20, rem = idx % 20;
                int g = rem / 5, cc = rem % 5;
                int soff = kp * G4 + g * 100 + (nb + 1) * 20 + cc * 4;
                int doff = (kp * B_STR + g * 20 + cc * 4) * 4;
                cpasync16(bhs + doff, g_wi_hi + soff);
                cpasync16(bls + doff, g_wi_lo + soff);
            }
            asm volatile("cp.async.commit_group;");
            asm volatile("cp.async.wait_group 1;");   // block nb's data ready
        } else {
            asm volatile("cp.async.wait_group 0;");
        }
        __syncthreads();   // B(nb) + (nb==0: A tile) visible to all

        uint32_t* b_hi = bufc;
        uint32_t* b_lo = bufc + 64 * B_STR;

        float accH[10][4], accL[10][4];
#pragma unroll
        for (int nt = 0; nt < 10; nt++)
#pragma unroll
            for (int q = 0; q < 4; q++) { accH[nt][q] = 0.f; accL[nt][q] = 0.f; }

#pragma unroll
        for (int kk = 0; kk < 8; kk++) {
            const int kp0 = kk * 8 + tig;
            const int kp1 = kp0 + 4;
            uint32_t ah0 = ah_r0[kp0], ah1 = ah_r1[kp0];
            uint32_t ah2 = ah_r0[kp1], ah3 = ah_r1[kp1];
            uint32_t al0 = al_r0[kp0], al1 = al_r1[kp0];
            uint32_t al2 = al_r0[kp1], al3 = al_r1[kp1];
            const uint32_t* bh0p = b_hi + kp0 * B_STR + gid;
            const uint32_t* bh1p = b_hi + kp1 * B_STR + gid;
            const uint32_t* bl0p = b_lo + kp0 * B_STR + gid;
            const uint32_t* bl1p = b_lo + kp1 * B_STR + gid;
#pragma unroll
            for (int nt = 0; nt < 10; nt++) {
                uint32_t bh0 = bh0p[nt * 8], bh1 = bh1p[nt * 8];
                uint32_t bl0 = bl0p[nt * 8], bl1 = bl1p[nt * 8];
                mma_f16(accH[nt], ah0, ah1, ah2, ah3, bh0, bh1);
                mma_f16(accL[nt], ah0, ah1, ah2, ah3, bl0, bl1);
                mma_f16(accL[nt], al0, al1, al2, al3, bh0, bh1);
            }
        }
        __syncthreads();   // done reading B(nb); reuse its buffer as staging

        float* sout = (float*)bufc;
        const float INVL = 1.f / 2048.f;
#pragma unroll
        for (int nt = 0; nt < 10; nt++) {
            int n0c = nt * 8 + 2 * tig;
            int n1c = n0c + 1;
            int p0 = (n0c % 20) * 4 + n0c / 20;
            int p1 = (n1c % 20) * 4 + n1c / 20;
            sout[(r0w + gid) * SO_STR + p0]     = accH[nt][0] + accL[nt][0] * INVL;
            sout[(r0w + gid) * SO_STR + p1]     = accH[nt][1] + accL[nt][1] * INVL;
            sout[(r0w + gid + 8) * SO_STR + p0] = accH[nt][2] + accL[nt][2] * INVL;
            sout[(r0w + gid + 8) * SO_STR + p1] = accH[nt][3] + accL[nt][3] * INVL;
        }
        __syncthreads();

        // coalesced write-out: 64 rows x 20 float4 (+bias)
        float4* gout = (float4*)g_xz;
        const float* sb = sbh + nb * 80;
#pragma unroll
        for (int q = 0; q < 10; q++) {
            int i = tid + q * 128;
            int r = i / 20, c = i % 20;
            float4 v;
            v.x = sout[r * SO_STR + 4 * c + 0] + sb[4 * c + 0];
            v.y = sout[r * SO_STR + 4 * c + 1] + sb[4 * c + 1];
            v.z = sout[r * SO_STR + 4 * c + 2] + sb[4 * c + 2];
            v.w = sout[r * SO_STR + 4 * c + 3] + sb[4 * c + 3];
            gout[(size_t)(m0 + r) * 100 + nb * 20 + c] = v;
        }
        __syncthreads();   // staging reads done before buffer is re-prefetched
    }
}

// ---------------------------------------------------------------------------
// Kernel 2: TENSORIZED persistent LSTM + fused projection.
// (Byte-identical to R12, verified rel_err 3.8e-7.)
// ---------------------------------------------------------------------------
#define THREADS_L 320
#define NT_REC 5
#define BQ_STR 408
#define WD_STR 104
#define H2_STR 60

#define OFF_BHI  0
#define OFF_BLO  21216
#define OFF_WDHI 42432
#define OFF_WDLO 47840
#define OFF_H2HI 53248
#define OFF_H2LO 54208
#define OFF_BD   55168
#define SMEM_L_BYTES (55272 * 4)

__device__ __forceinline__ float sigf(float xv) {
    return __fdividef(1.f, 1.f + __expf(-xv));
}
__device__ __forceinline__ float tanh_f(float xv) {
    float e = __expf(2.f * xv);
    return 1.f - __fdividef(2.f, e + 1.f);
}

__global__ __launch_bounds__(THREADS_L, 1) void lstm_kernel(
    const float* __restrict__ Wh,
    const float* __restrict__ Wd,
    const float* __restrict__ bd,
    float* __restrict__ out)
{
    extern __shared__ uint32_t smL[];
    __half* Bhi_h  = (__half*)(smL + OFF_BHI);
    __half* Blo_h  = (__half*)(smL + OFF_BLO);
    __half* Wdhi_h = (__half*)(smL + OFF_WDHI);
    __half* Wdlo_h = (__half*)(smL + OFF_WDLO);
    __half* h2hi_h = (__half*)(smL + OFF_H2HI);
    __half* h2lo_h = (__half*)(smL + OFF_H2LO);
    float*  sbd    = (float*)(smL + OFF_BD);

    const int tid = threadIdx.x;

    for (int i = tid; i < 2 * BQ_STR; i += THREADS_L) {
        smL[OFF_BHI + 50 * BQ_STR + i] = 0;
        smL[OFF_BLO + 50 * BQ_STR + i] = 0;
    }
    for (int i = tid; i < 52 * WD_STR; i += THREADS_L) {
        smL[OFF_WDHI + i] = 0;
        smL[OFF_WDLO + i] = 0;
    }
    for (int i = tid; i < 16 * H2_STR; i += THREADS_L) {
        smL[OFF_H2HI + i] = 0;
        smL[OFF_H2LO + i] = 0;
    }
    if (tid < 104) sbd[tid] = (tid < HID) ? bd[tid] : 0.f;
    __syncthreads();

    for (int i = tid; i < HID * G4; i += THREADS_L) {
        int k = i / G4, c = i - k * G4;
        int g = c / HID, j = c - g * HID;
        int colp = 4 * j + g;
        float w = Wh[i];
        __half h = __float2half_rn(w);
        __half l = __float2half_rn((w - __half2float(h)) * 2048.f);
        int hidx = (k >> 1) * (2 * BQ_STR) + colp * 2 + (k & 1);
        Bhi_h[hidx] = h;
        Blo_h[hidx] = l;
    }
    for (int i = tid; i < HID * HID; i += THREADS_L) {
        int k = i / HID, j = i - k * HID;
        float w = Wd[i];
        __half h = __float2half_rn(w);
        __half l = __float2half_rn((w - __half2float(h)) * 2048.f);
        int hidx = (k >> 1) * (2 * WD_STR) + j * 2 + (k & 1);
        Wdhi_h[hidx] = h;
        Wdlo_h[hidx] = l;
    }
    __syncthreads();

    const int warp = tid >> 5, lane = tid & 31;
    const int gid = lane >> 2, tig = lane & 3;
    const int r0c = blockIdx.x * 16;
    const int ntb = warp * NT_REC;
    const int pstart = (warp < 3) ? 2 * warp : warp + 3;
    const int pcnt   = (warp < 3) ? 2 : 1;

    const uint32_t h2hi_b = sptr(h2hi_h) + (lane & 15) * (H2_STR * 4)
                          + (lane >> 4) * 16;
    const uint32_t h2lo_b = sptr(h2lo_h) + (lane & 15) * (H2_STR * 4)
                          + (lane >> 4) * 16;

    const int cj   = tig >> 1;
    const int crow = gid + (tig & 1) * 8;

    float cst[NT_REC];
#pragma unroll
    for (int s = 0; s < NT_REC; s++) cst[s] = 0.f;

    const float4* xzg = (const float4*)g_xz;
    const float INVL = 1.f / 2048.f;

    for (int t = 0; t < TSTEPS; t++) {
        float4 xzc[NT_REC];
#pragma unroll
        for (int s = 0; s < NT_REC; s++) {
            int j = 2 * (ntb + s) + cj;
            xzc[s] = __ldcs(xzg + ((size_t)(r0c + crow) * TSTEPS + t) * HID + j);
        }

        float accH[NT_REC][4], accL[NT_REC][4];
        float pacH[2][4], pacL[2][4];
#pragma unroll
        for (int s = 0; s < NT_REC; s++)
#pragma unroll
            for (int q = 0; q < 4; q++) { accH[s][q] = 0.f; accL[s][q] = 0.f; }
#pragma unroll
        for (int p = 0; p < 2; p++)
#pragma unroll
            for (int q = 0; q < 4; q++) { pacH[p][q] = 0.f; pacL[p][q] = 0.f; }

#pragma unroll
        for (int kc = 0; kc < 6; kc++) {
            uint32_t ah0, ah1, ah2, ah3, al0, al1, al2, al3;
            ldmx4(ah0, ah1, ah2, ah3, h2hi_b + kc * 32);
            ldmx4(al0, al1, al2, al3, h2lo_b + kc * 32);

            const uint32_t* Bh0 = smL + OFF_BHI + (kc * 8 + tig) * BQ_STR + gid;
            const uint32_t* Bl0 = smL + OFF_BLO + (kc * 8 + tig) * BQ_STR + gid;
#pragma unroll
            for (int s = 0; s < NT_REC; s++) {
                int off = (ntb + s) * 8;
                uint32_t b0h = Bh0[off], b1h = Bh0[off + 4 * BQ_STR];
                uint32_t b0l = Bl0[off], b1l = Bl0[off + 4 * BQ_STR];
                mma_f16(accH[s], ah0, ah1, ah2, ah3, b0h, b1h);
                mma_f16(accL[s], ah0, ah1, ah2, ah3, b0l, b1l);
                mma_f16(accL[s], al0, al1, al2, al3, b0h, b1h);
            }
            const uint32_t* Wh0 = smL + OFF_WDHI + (kc * 8 + tig) * WD_STR + gid;
            const uint32_t* Wl0 = smL + OFF_WDLO + (kc * 8 + tig) * WD_STR + gid;
#pragma unroll
            for (int p = 0; p < 2; p++) {
                if (p < pcnt) {
                    int off = (pstart + p) * 8;
                    uint32_t b0h = Wh0[off], b1h = Wh0[off + 4 * WD_STR];
                    uint32_t b0l = Wl0[off], b1l = Wl0[off + 4 * WD_STR];
                    mma_f16(pacH[p], ah0, ah1, ah2, ah3, b0h, b1h);
                    mma_f16(pacL[p], ah0, ah1, ah2, ah3, b0l, b1l);
                    mma_f16(pacL[p], al0, al1, al2, al3, b0h, b1h);
                }
            }
        }
        {
            uint32_t ah0, ah1, al0, al1;
            ldmx2(ah0, ah1, h2hi_b + 192);
            ldmx2(al0, al1, h2lo_b + 192);
            const uint32_t* Bh = smL + OFF_BHI + (48 + tig) * BQ_STR + gid;
            const uint32_t* Bl = smL + OFF_BLO + (48 + tig) * BQ_STR + gid;
#pragma unroll
            for (int s = 0; s < NT_REC; s++) {
                int off = (ntb + s) * 8;
                uint32_t b0h = Bh[off], b0l = Bl[off];
                mma_f16_k8(accH[s], ah0, ah1, b0h);
                mma_f16_k8(accL[s], ah0, ah1, b0l);
                mma_f16_k8(accL[s], al0, al1, b0h);
            }
            const uint32_t* Wh0 = smL + OFF_WDHI + (48 + tig) * WD_STR + gid;
            const uint32_t* Wl0 = smL + OFF_WDLO + (48 + tig) * WD_STR + gid;
#pragma unroll
            for (int p = 0; p < 2; p++) {
                if (p < pcnt) {
                    int off = (pstart + p) * 8;
                    uint32_t b0h = Wh0[off], b0l = Wl0[off];
                    mma_f16_k8(pacH[p], ah0, ah1, b0h);
                    mma_f16_k8(pacL[p], ah0, ah1, b0l);
                    mma_f16_k8(pacL[p], al0, al1, b0h);
                }
            }
        }

        if (t > 0) {
#pragma unroll
            for (int p = 0; p < 2; p++) {
                if (p < pcnt) {
                    int c0 = (pstart + p) * 8 + 2 * tig;
                    if (c0 <= 98) {
                        float b0 = sbd[c0], b1 = sbd[c0 + 1];
                        float v0 = fmaxf(pacH[p][0] + pacL[p][0] * INVL + b0, 0.f);
                        float v1 = fmaxf(pacH[p][1] + pacL[p][1] * INVL + b1, 0.f);
                        float v2 = fmaxf(pacH[p][2] + pacL[p][2] * INVL + b0, 0.f);
                        float v3 = fmaxf(pacH[p][3] + pacL[p][3] * INVL + b1, 0.f);
                        *(float2*)(out + ((size_t)(r0c + gid) * TSTEPS + (t - 1)) * HID + c0)
                            = make_float2(v0, v1);
                        *(float2*)(out + ((size_t)(r0c + gid + 8) * TSTEPS + (t - 1)) * HID + c0)
                            = make_float2(v2, v3);
                    }
                }
            }
        }

        __syncthreads();

#pragma unroll
        for (int s = 0; s < NT_REC; s++) {
            float z0 = accH[s][0] + accL[s][0] * INVL;
            float z1 = accH[s][1] + accL[s][1] * INVL;
            float z2 = accH[s][2] + accL[s][2] * INVL;
            float z3 = accH[s][3] + accL[s][3] * INVL;
            float x0 = __shfl_xor_sync(0xffffffffu, z0, 1);
            float x1 = __shfl_xor_sync(0xffffffffu, z1, 1);
            float x2 = __shfl_xor_sync(0xffffffffu, z2, 1);
            float x3 = __shfl_xor_sync(0xffffffffu, z3, 1);
            float zi, zf, zg, zo;
            if ((tig & 1) == 0) { zi = z0; zf = z1; zg = x0; zo = x1; }
            else                { zi = x2; zf = x3; zg = z2; zo = z3; }
            zi += xzc[s].x; zf += xzc[s].y; zg += xzc[s].z; zo += xzc[s].w;
            float ig = sigf(zi), fg = sigf(zf);
            float gg = tanh_f(zg), og = sigf(zo);
            float c = fg * cst[s] + ig * gg;
            cst[s] = c;
            float h = og * tanh_f(c);
            __half hh = __float2half_rn(h);
            __half hl = __float2half_rn((h - __half2float(hh)) * 2048.f);
            int j = 2 * (ntb + s) + cj;
            h2hi_h[crow * (H2_STR * 2) + j] = hh;
            h2lo_h[crow * (H2_STR * 2) + j] = hl;
        }
        __syncthreads();
    }

    {
        float pacH[2][4], pacL[2][4];
#pragma unroll
        for (int p = 0; p < 2; p++)
#pragma unroll
            for (int q = 0; q < 4; q++) { pacH[p][q] = 0.f; pacL[p][q] = 0.f; }

#pragma unroll
        for (int kc = 0; kc < 6; kc++) {
            uint32_t ah0, ah1, ah2, ah3, al0, al1, al2, al3;
            ldmx4(ah0, ah1, ah2, ah3, h2hi_b + kc * 32);
            ldmx4(al0, al1, al2, al3, h2lo_b + kc * 32);
            const uint32_t* Wh0 = smL + OFF_WDHI + (kc * 8 + tig) * WD_STR + gid;
            const uint32_t* Wl0 = smL + OFF_WDLO + (kc * 8 + tig) * WD_STR + gid;
#pragma unroll
            for (int p = 0; p < 2; p++) {
                if (p < pcnt) {
                    int off = (pstart + p) * 8;
                    uint32_t b0h = Wh0[off], b1h = Wh0[off + 4 * WD_STR];
                    uint32_t b0l = Wl0[off], b1l = Wl0[off + 4 * WD_STR];
                    mma_f16(pacH[p], ah0, ah1, ah2, ah3, b0h, b1h);
                    mma_f16(pacL[p], ah0, ah1, ah2, ah3, b0l, b1l);
                    mma_f16(pacL[p], al0, al1, al2, al3, b0h, b1h);
                }
            }
        }
        {
            uint32_t ah0, ah1, al0, al1;
            ldmx2(ah0, ah1, h2hi_b + 192);
            ldmx2(al0, al1, h2lo_b + 192);
            const uint32_t* Wh0 = smL + OFF_WDHI + (48 + tig) * WD_STR + gid;
            const uint32_t* Wl0 = smL + OFF_WDLO + (48 + tig) * WD_STR + gid;
#pragma unroll
            for (int p = 0; p < 2; p++) {
                if (p < pcnt) {
                    int off = (pstart + p) * 8;
                    uint32_t b0h = Wh0[off], b0l = Wl0[off];
                    mma_f16_k8(pacH[p], ah0, ah1, b0h);
                    mma_f16_k8(pacL[p], ah0, ah1, b0l);
                    mma_f16_k8(pacL[p], al0, al1, b0h);
                }
            }
        }
#pragma unroll
        for (int p = 0; p < 2; p++) {
            if (p < pcnt) {
                int c0 = (pstart + p) * 8 + 2 * tig;
                if (c0 <= 98) {
                    float b0 = sbd[c0], b1 = sbd[c0 + 1];
                    float v0 = fmaxf(pacH[p][0] + pacL[p][0] * INVL + b0, 0.f);
                    float v1 = fmaxf(pacH[p][1] + pacL[p][1] * INVL + b1, 0.f);
                    float v2 = fmaxf(pacH[p][2] + pacL[p][2] * INVL + b0, 0.f);
                    float v3 = fmaxf(pacH[p][3] + pacL[p][3] * INVL + b1, 0.f);
                    *(float2*)(out + ((size_t)(r0c + gid) * TSTEPS + (TSTEPS - 1)) * HID + c0)
                        = make_float2(v0, v1);
                    *(float2*)(out + ((size_t)(r0c + gid + 8) * TSTEPS + (TSTEPS - 1)) * HID + c0)
                        = make_float2(v2, v3);
                }
            }
        }
    }
}

// ---------------------------------------------------------------------------
// Launch
// ---------------------------------------------------------------------------
extern "C" void kernel_launch(void* const* d_in, const int* in_sizes, int n_in,
                              void* d_out, int out_size)
{
    const float* x  = (const float*)d_in[0];   // [2048,250,128]
    const float* Wi = (const float*)d_in[1];   // [128,400]
    const float* Wh = (const float*)d_in[2];   // [100,400]
    const float* bh = (const float*)d_in[3];   // [400]
    const float* Wd = (const float*)d_in[4];   // [100,100]
    const float* bd = (const float*)d_in[5];   // [100]
    float* out = (float*)d_out;                // [2048,250,100]

    cudaFuncSetAttribute(gemm_xz_kernel,
                         cudaFuncAttributeMaxDynamicSharedMemorySize, G_SMEM_BYTES);
    cudaFuncSetAttribute(lstm_kernel,
                         cudaFuncAttributeMaxDynamicSharedMemorySize, SMEM_L_BYTES);

    wi_split_kernel<<<(64 * G4 + 255) / 256, 256>>>(Wi);
    gemm_xz_kernel<<<MTOT / BM, 128, G_SMEM_BYTES>>>(x, bh);
    lstm_kernel<<<BATCH / 16, THREADS_L, SMEM_L_BYTES>>>(Wh, Wd, bd, out);
}

// round 17
// speedup vs baseline: 1.0191x; 1.0191x over previous
#include <cuda_runtime.h>
#include <cuda_fp16.h>
#include <cstdint>

#define BATCH   2048
#define TSTEPS  250
#define DIN     128
#define HID     100
#define G4      400
#define MTOT    (BATCH*TSTEPS)

// Scratch for xz : GATE-INTERLEAVED layout [m][j][g]  (index = m*400 + j*4 + g)
__device__ float g_xz[(size_t)MTOT * G4];
// Pre-split Wi (written once per launch): [kp][gcol] f16x2 hi / scaled-lo
__device__ uint32_t g_wi_hi[64 * G4];
__device__ uint32_t g_wi_lo[64 * G4];
// Pre-split x (written once per launch): [m][kp] f16x2 hi / scaled-lo
__device__ uint32_t g_x_hi[(size_t)MTOT * 64];
__device__ uint32_t g_x_lo[(size_t)MTOT * 64];

// ---------------------------------------------------------------------------
// helpers
// ---------------------------------------------------------------------------
__device__ __forceinline__ uint32_t sptr(const void* p) {
    return (uint32_t)__cvta_generic_to_shared(p);
}
__device__ __forceinline__ void cpasync16(uint32_t dst, const void* src) {
    asm volatile("cp.async.ca.shared.global [%0], [%1], 16;" :: "r"(dst), "l"(src));
}
__device__ __forceinline__ void mma_f16(float c[4], uint32_t a0, uint32_t a1,
                                        uint32_t a2, uint32_t a3,
                                        uint32_t b0, uint32_t b1) {
    asm volatile(
        "mma.sync.aligned.m16n8k16.row.col.f32.f16.f16.f32 "
        "{%0,%1,%2,%3}, {%4,%5,%6,%7}, {%8,%9}, {%0,%1,%2,%3};"
        : "+f"(c[0]), "+f"(c[1]), "+f"(c[2]), "+f"(c[3])
        : "r"(a0), "r"(a1), "r"(a2), "r"(a3), "r"(b0), "r"(b1));
}
__device__ __forceinline__ void mma_f16_k8(float c[4], uint32_t a0, uint32_t a1,
                                           uint32_t b0) {
    asm volatile(
        "mma.sync.aligned.m16n8k8.row.col.f32.f16.f16.f32 "
        "{%0,%1,%2,%3}, {%4,%5}, {%6}, {%0,%1,%2,%3};"
        : "+f"(c[0]), "+f"(c[1]), "+f"(c[2]), "+f"(c[3])
        : "r"(a0), "r"(a1), "r"(b0));
}
__device__ __forceinline__ void ldmx4(uint32_t& r0, uint32_t& r1,
                                      uint32_t& r2, uint32_t& r3, uint32_t a) {
    asm volatile("ldmatrix.sync.aligned.m8n8.x4.shared.b16 {%0,%1,%2,%3}, [%4];"
        : "=r"(r0), "=r"(r1), "=r"(r2), "=r"(r3) : "r"(a));
}
__device__ __forceinline__ void ldmx2(uint32_t& r0, uint32_t& r1, uint32_t a) {
    asm volatile("ldmatrix.sync.aligned.m8n8.x2.shared.b16 {%0,%1}, [%2];"
        : "=r"(r0), "=r"(r1) : "r"(a));
}

// ---------------------------------------------------------------------------
// Kernel 0a: pre-split Wi into hi/lo f16x2 k-pair layout (once per launch).
// ---------------------------------------------------------------------------
__global__ __launch_bounds__(256) void wi_split_kernel(
    const float* __restrict__ Wi)
{
    int i = blockIdx.x * 256 + threadIdx.x;     // over 64*400 k-pair x col
    if (i >= 64 * G4) return;
    int kp = i / G4, c = i - kp * G4;
    float f0 = Wi[(size_t)(2 * kp) * G4 + c];
    float f1 = Wi[(size_t)(2 * kp + 1) * G4 + c];
    __half2 h = __floats2half2_rn(f0, f1);
    float2 hf = __half22float2(h);
    __half2 l = __floats2half2_rn((f0 - hf.x) * 2048.f,
                                  (f1 - hf.y) * 2048.f);
    g_wi_hi[i] = *(uint32_t*)&h;
    g_wi_lo[i] = *(uint32_t*)&l;
}

// ---------------------------------------------------------------------------
// Kernel 0b: pre-split x into hi/lo f16x2 k-pair layout (once per launch).
// Bit-identical split math to the in-gemm version of the 1685us kernel.
// ---------------------------------------------------------------------------
__global__ __launch_bounds__(256) void x_split_kernel(
    const float* __restrict__ x)
{
    size_t i = (size_t)blockIdx.x * 256 + threadIdx.x;  // over MTOT*64 k-pairs
    if (i >= (size_t)MTOT * 64) return;
    float2 v = *(const float2*)(x + 2 * i);
    __half2 h = __floats2half2_rn(v.x, v.y);
    float2 hf = __half22float2(h);
    __half2 l = __floats2half2_rn((v.x - hf.x) * 2048.f,
                                  (v.y - hf.y) * 2048.f);
    g_x_hi[i] = *(uint32_t*)&h;
    g_x_lo[i] = *(uint32_t*)&l;
}

// ---------------------------------------------------------------------------
// Kernel 1: xz = x@Wi + bh via fp16 split-3 mma.sync (math identical to the
// 1685us best). Prologue is PURE cp.async: both A (x) and B (Wi) tiles arrive
// pre-split from global. Grid 8000 x 5.
// ---------------------------------------------------------------------------
#define BM 64
#define A_STR 68
#define B_STR 104
#define SO_STR 84

__global__ __launch_bounds__(128) void gemm_xz_kernel(
    const float* __restrict__ bh)
{
    extern __shared__ uint32_t smg[];
    uint32_t* a_hi = smg;
    uint32_t* a_lo = a_hi + 64 * A_STR;
    uint32_t* b_hi = a_lo + 64 * A_STR;
    uint32_t* b_lo = b_hi + 64 * B_STR;
    float*    sbh  = (float*)(b_lo + 64 * B_STR);
    float*    sout = (float*)b_lo;

    const int tid = threadIdx.x;
    const size_t m0 = (size_t)blockIdx.x * BM;
    const int j0  = blockIdx.y * 20;

    if (tid < 80) sbh[tid] = bh[(tid & 3) * 100 + j0 + (tid >> 2)];

    // B (Wi) tiles: cp.async of pre-split data
    {
        const uint32_t bhs = sptr(b_hi);
        const uint32_t bls = sptr(b_lo);
#pragma unroll
        for (int q = 0; q < 10; q++) {
            int idx = tid + q * 128;            // 0..1279
            int kp = idx / 20, rem = idx % 20;
            int g = rem / 5, cc = rem % 5;
            int soff = kp * G4 + g * 100 + j0 + cc * 4;
            int doff = (kp * B_STR + g * 20 + cc * 4) * 4;
            cpasync16(bhs + doff, g_wi_hi + soff);
            cpasync16(bls + doff, g_wi_lo + soff);
        }
    }
    // A (x) tiles: cp.async of pre-split data (64 rows x 16 16B-chunks each)
    {
        const uint32_t ahs = sptr(a_hi);
        const uint32_t als = sptr(a_lo);
#pragma unroll
        for (int q = 0; q < 8; q++) {
            int idx = tid + q * 128;            // 0..1023
            int r = idx >> 4, ch = idx & 15;
            uint32_t doff = (uint32_t)(r * A_STR + ch * 4) * 4;
            cpasync16(ahs + doff, g_x_hi + (m0 + r) * 64 + ch * 4);
            cpasync16(als + doff, g_x_lo + (m0 + r) * 64 + ch * 4);
        }
    }
    asm volatile("cp.async.commit_group;");
    asm volatile("cp.async.wait_group 0;");
    __syncthreads();

    const int warp = tid >> 5, lane = tid & 31;
    const int gid = lane >> 2, tig = lane & 3;
    const int r0w = warp * 16;

    float accH[10][4], accL[10][4];
#pragma unroll
    for (int nt = 0; nt < 10; nt++)
#pragma unroll
        for (int q = 0; q < 4; q++) { accH[nt][q] = 0.f; accL[nt][q] = 0.f; }

    const uint32_t* ah_r0 = a_hi + (r0w + gid) * A_STR;
    const uint32_t* ah_r1 = a_hi + (r0w + gid + 8) * A_STR;
    const uint32_t* al_r0 = a_lo + (r0w + gid) * A_STR;
    const uint32_t* al_r1 = a_lo + (r0w + gid + 8) * A_STR;

#pragma unroll
    for (int kk = 0; kk < 8; kk++) {
        const int kp0 = kk * 8 + tig;
        const int kp1 = kp0 + 4;
        uint32_t ah0 = ah_r0[kp0], ah1 = ah_r1[kp0];
        uint32_t ah2 = ah_r0[kp1], ah3 = ah_r1[kp1];
        uint32_t al0 = al_r0[kp0], al1 = al_r1[kp0];
        uint32_t al2 = al_r0[kp1], al3 = al_r1[kp1];
        const uint32_t* bh0p = b_hi + kp0 * B_STR + gid;
        const uint32_t* bh1p = b_hi + kp1 * B_STR + gid;
        const uint32_t* bl0p = b_lo + kp0 * B_STR + gid;
        const uint32_t* bl1p = b_lo + kp1 * B_STR + gid;
#pragma unroll
        for (int nt = 0; nt < 10; nt++) {
            uint32_t bh0 = bh0p[nt * 8], bh1 = bh1p[nt * 8];
            uint32_t bl0 = bl0p[nt * 8], bl1 = bl1p[nt * 8];
            mma_f16(accH[nt], ah0, ah1, ah2, ah3, bh0, bh1);
            mma_f16(accL[nt], ah0, ah1, ah2, ah3, bl0, bl1);
            mma_f16(accL[nt], al0, al1, al2, al3, bh0, bh1);
        }
    }
    __syncthreads();   // done reading b_lo; reuse as staging

    const float INVL = 1.f / 2048.f;
#pragma unroll
    for (int nt = 0; nt < 10; nt++) {
        int n0c = nt * 8 + 2 * tig;
        int n1c = n0c + 1;
        int p0 = (n0c % 20) * 4 + n0c / 20;
        int p1 = (n1c % 20) * 4 + n1c / 20;
        sout[(r0w + gid) * SO_STR + p0]     = accH[nt][0] + accL[nt][0] * INVL;
        sout[(r0w + gid) * SO_STR + p1]     = accH[nt][1] + accL[nt][1] * INVL;
        sout[(r0w + gid + 8) * SO_STR + p0] = accH[nt][2] + accL[nt][2] * INVL;
        sout[(r0w + gid + 8) * SO_STR + p1] = accH[nt][3] + accL[nt][3] * INVL;
    }
    __syncthreads();

    float4* gout = (float4*)g_xz;
#pragma unroll
    for (int q = 0; q < 10; q++) {
        int i = tid + q * 128;
        int r = i / 20, c = i % 20;
        float4 v;
        v.x = sout[r * SO_STR + 4 * c + 0] + sbh[4 * c + 0];
        v.y = sout[r * SO_STR + 4 * c + 1] + sbh[4 * c + 1];
        v.z = sout[r * SO_STR + 4 * c + 2] + sbh[4 * c + 2];
        v.w = sout[r * SO_STR + 4 * c + 3] + sbh[4 * c + 3];
        gout[(m0 + r) * 100 + 20 * blockIdx.y + c] = v;
    }
}

// ---------------------------------------------------------------------------
// Kernel 2: TENSORIZED persistent LSTM + fused projection.
// BYTE-IDENTICAL to the proven R12/R13 version (1685us, rel_err 3.818e-7):
// single h buffer, TWO barriers per step.
// ---------------------------------------------------------------------------
#define THREADS_L 320
#define NT_REC 5
#define BQ_STR 408
#define WD_STR 104
#define H2_STR 60

#define OFF_BHI  0
#define OFF_BLO  21216
#define OFF_WDHI 42432
#define OFF_WDLO 47840
#define OFF_H2HI 53248
#define OFF_H2LO 54208
#define OFF_BD   55168
#define SMEM_L_BYTES (55272 * 4)

__device__ __forceinline__ float sigf(float xv) {
    return __fdividef(1.f, 1.f + __expf(-xv));
}
__device__ __forceinline__ float tanh_f(float xv) {
    float e = __expf(2.f * xv);
    return 1.f - __fdividef(2.f, e + 1.f);
}

__global__ __launch_bounds__(THREADS_L, 1) void lstm_kernel(
    const float* __restrict__ Wh,
    const float* __restrict__ Wd,
    const float* __restrict__ bd,
    float* __restrict__ out)
{
    extern __shared__ uint32_t smL[];
    __half* Bhi_h  = (__half*)(smL + OFF_BHI);
    __half* Blo_h  = (__half*)(smL + OFF_BLO);
    __half* Wdhi_h = (__half*)(smL + OFF_WDHI);
    __half* Wdlo_h = (__half*)(smL + OFF_WDLO);
    __half* h2hi_h = (__half*)(smL + OFF_H2HI);
    __half* h2lo_h = (__half*)(smL + OFF_H2LO);
    float*  sbd    = (float*)(smL + OFF_BD);

    const int tid = threadIdx.x;

    for (int i = tid; i < 2 * BQ_STR; i += THREADS_L) {
        smL[OFF_BHI + 50 * BQ_STR + i] = 0;
        smL[OFF_BLO + 50 * BQ_STR + i] = 0;
    }
    for (int i = tid; i < 52 * WD_STR; i += THREADS_L) {
        smL[OFF_WDHI + i] = 0;
        smL[OFF_WDLO + i] = 0;
    }
    for (int i = tid; i < 16 * H2_STR; i += THREADS_L) {
        smL[OFF_H2HI + i] = 0;
        smL[OFF_H2LO + i] = 0;
    }
    if (tid < 104) sbd[tid] = (tid < HID) ? bd[tid] : 0.f;
    __syncthreads();

    for (int i = tid; i < HID * G4; i += THREADS_L) {
        int k = i / G4, c = i - k * G4;
        int g = c / HID, j = c - g * HID;
        int colp = 4 * j + g;
        float w = Wh[i];
        __half h = __float2half_rn(w);
        __half l = __float2half_rn((w - __half2float(h)) * 2048.f);
        int hidx = (k >> 1) * (2 * BQ_STR) + colp * 2 + (k & 1);
        Bhi_h[hidx] = h;
        Blo_h[hidx] = l;
    }
    for (int i = tid; i < HID * HID; i += THREADS_L) {
        int k = i / HID, j = i - k * HID;
        float w = Wd[i];
        __half h = __float2half_rn(w);
        __half l = __float2half_rn((w - __half2float(h)) * 2048.f);
        int hidx = (k >> 1) * (2 * WD_STR) + j * 2 + (k & 1);
        Wdhi_h[hidx] = h;
        Wdlo_h[hidx] = l;
    }
    __syncthreads();

    const int warp = tid >> 5, lane = tid & 31;
    const int gid = lane >> 2, tig = lane & 3;
    const int r0c = blockIdx.x * 16;
    const int ntb = warp * NT_REC;
    const int pstart = (warp < 3) ? 2 * warp : warp + 3;
    const int pcnt   = (warp < 3) ? 2 : 1;

    const uint32_t h2hi_b = sptr(h2hi_h) + (lane & 15) * (H2_STR * 4)
                          + (lane >> 4) * 16;
    const uint32_t h2lo_b = sptr(h2lo_h) + (lane & 15) * (H2_STR * 4)
                          + (lane >> 4) * 16;

    const int cj   = tig >> 1;
    const int crow = gid + (tig & 1) * 8;

    float cst[NT_REC];
#pragma unroll
    for (int s = 0; s < NT_REC; s++) cst[s] = 0.f;

    const float4* xzg = (const float4*)g_xz;
    const float INVL = 1.f / 2048.f;

    for (int t = 0; t < TSTEPS; t++) {
        float4 xzc[NT_REC];
#pragma unroll
        for (int s = 0; s < NT_REC; s++) {
            int j = 2 * (ntb + s) + cj;
            xzc[s] = __ldcs(xzg + ((size_t)(r0c + crow) * TSTEPS + t) * HID + j);
        }

        float accH[NT_REC][4], accL[NT_REC][4];
        float pacH[2][4], pacL[2][4];
#pragma unroll
        for (int s = 0; s < NT_REC; s++)
#pragma unroll
            for (int q = 0; q < 4; q++) { accH[s][q] = 0.f; accL[s][q] = 0.f; }
#pragma unroll
        for (int p = 0; p < 2; p++)
#pragma unroll
            for (int q = 0; q < 4; q++) { pacH[p][q] = 0.f; pacL[p][q] = 0.f; }

#pragma unroll
        for (int kc = 0; kc < 6; kc++) {
            uint32_t ah0, ah1, ah2, ah3, al0, al1, al2, al3;
            ldmx4(ah0, ah1, ah2, ah3, h2hi_b + kc * 32);
            ldmx4(al0, al1, al2, al3, h2lo_b + kc * 32);

            const uint32_t* Bh0 = smL + OFF_BHI + (kc * 8 + tig) * BQ_STR + gid;
            const uint32_t* Bl0 = smL + OFF_BLO + (kc * 8 + tig) * BQ_STR + gid;
#pragma unroll
            for (int s = 0; s < NT_REC; s++) {
                int off = (ntb + s) * 8;
                uint32_t b0h = Bh0[off], b1h = Bh0[off + 4 * BQ_STR];
                uint32_t b0l = Bl0[off], b1l = Bl0[off + 4 * BQ_STR];
                mma_f16(accH[s], ah0, ah1, ah2, ah3, b0h, b1h);
                mma_f16(accL[s], ah0, ah1, ah2, ah3, b0l, b1l);
                mma_f16(accL[s], al0, al1, al2, al3, b0h, b1h);
            }
            const uint32_t* Wh0 = smL + OFF_WDHI + (kc * 8 + tig) * WD_STR + gid;
            const uint32_t* Wl0 = smL + OFF_WDLO + (kc * 8 + tig) * WD_STR + gid;
#pragma unroll
            for (int p = 0; p < 2; p++) {
                if (p < pcnt) {
                    int off = (pstart + p) * 8;
                    uint32_t b0h = Wh0[off], b1h = Wh0[off + 4 * WD_STR];
                    uint32_t b0l = Wl0[off], b1l = Wl0[off + 4 * WD_STR];
                    mma_f16(pacH[p], ah0, ah1, ah2, ah3, b0h, b1h);
                    mma_f16(pacL[p], ah0, ah1, ah2, ah3, b0l, b1l);
                    mma_f16(pacL[p], al0, al1, al2, al3, b0h, b1h);
                }
            }
        }
        {
            uint32_t ah0, ah1, al0, al1;
            ldmx2(ah0, ah1, h2hi_b + 192);
            ldmx2(al0, al1, h2lo_b + 192);
            const uint32_t* Bh = smL + OFF_BHI + (48 + tig) * BQ_STR + gid;
            const uint32_t* Bl = smL + OFF_BLO + (48 + tig) * BQ_STR + gid;
#pragma unroll
            for (int s = 0; s < NT_REC; s++) {
                int off = (ntb + s) * 8;
                uint32_t b0h = Bh[off], b0l = Bl[off];
                mma_f16_k8(accH[s], ah0, ah1, b0h);
                mma_f16_k8(accL[s], ah0, ah1, b0l);
                mma_f16_k8(accL[s], al0, al1, b0h);
            }
            const uint32_t* Wh0 = smL + OFF_WDHI + (48 + tig) * WD_STR + gid;
            const uint32_t* Wl0 = smL + OFF_WDLO + (48 + tig) * WD_STR + gid;
#pragma unroll
            for (int p = 0; p < 2; p++) {
                if (p < pcnt) {
                    int off = (pstart + p) * 8;
                    uint32_t b0h = Wh0[off], b0l = Wl0[off];
                    mma_f16_k8(pacH[p], ah0, ah1, b0h);
                    mma_f16_k8(pacL[p], ah0, ah1, b0l);
                    mma_f16_k8(pacL[p], al0, al1, b0h);
                }
            }
        }

        if (t > 0) {
#pragma unroll
            for (int p = 0; p < 2; p++) {
                if (p < pcnt) {
                    int c0 = (pstart + p) * 8 + 2 * tig;
                    if (c0 <= 98) {
                        float b0 = sbd[c0], b1 = sbd[c0 + 1];
                        float v0 = fmaxf(pacH[p][0] + pacL[p][0] * INVL + b0, 0.f);
                        float v1 = fmaxf(pacH[p][1] + pacL[p][1] * INVL + b1, 0.f);
                        float v2 = fmaxf(pacH[p][2] + pacL[p][2] * INVL + b0, 0.f);
                        float v3 = fmaxf(pacH[p][3] + pacL[p][3] * INVL + b1, 0.f);
                        *(float2*)(out + ((size_t)(r0c + gid) * TSTEPS + (t - 1)) * HID + c0)
                            = make_float2(v0, v1);
                        *(float2*)(out + ((size_t)(r0c + gid + 8) * TSTEPS + (t - 1)) * HID + c0)
                            = make_float2(v2, v3);
                    }
                }
            }
        }

        __syncthreads();

#pragma unroll
        for (int s = 0; s < NT_REC; s++) {
            float z0 = accH[s][0] + accL[s][0] * INVL;
            float z1 = accH[s][1] + accL[s][1] * INVL;
            float z2 = accH[s][2] + accL[s][2] * INVL;
            float z3 = accH[s][3] + accL[s][3] * INVL;
            float x0 = __shfl_xor_sync(0xffffffffu, z0, 1);
            float x1 = __shfl_xor_sync(0xffffffffu, z1, 1);
            float x2 = __shfl_xor_sync(0xffffffffu, z2, 1);
            float x3 = __shfl_xor_sync(0xffffffffu, z3, 1);
            float zi, zf, zg, zo;
            if ((tig & 1) == 0) { zi = z0; zf = z1; zg = x0; zo = x1; }
            else                { zi = x2; zf = x3; zg = z2; zo = z3; }
            zi += xzc[s].x; zf += xzc[s].y; zg += xzc[s].z; zo += xzc[s].w;
            float ig = sigf(zi), fg = sigf(zf);
            float gg = tanh_f(zg), og = sigf(zo);
            float c = fg * cst[s] + ig * gg;
            cst[s] = c;
            float h = og * tanh_f(c);
            __half hh = __float2half_rn(h);
            __half hl = __float2half_rn((h - __half2float(hh)) * 2048.f);
            int j = 2 * (ntb + s) + cj;
            h2hi_h[crow * (H2_STR * 2) + j] = hh;
            h2lo_h[crow * (H2_STR * 2) + j] = hl;
        }
        __syncthreads();
    }

    {
        float pacH[2][4], pacL[2][4];
#pragma unroll
        for (int p = 0; p < 2; p++)
#pragma unroll
            for (int q = 0; q < 4; q++) { pacH[p][q] = 0.f; pacL[p][q] = 0.f; }

#pragma unroll
        for (int kc = 0; kc < 6; kc++) {
            uint32_t ah0, ah1, ah2, ah3, al0, al1, al2, al3;
            ldmx4(ah0, ah1, ah2, ah3, h2hi_b + kc * 32);
            ldmx4(al0, al1, al2, al3, h2lo_b + kc * 32);
            const uint32_t* Wh0 = smL + OFF_WDHI + (kc * 8 + tig) * WD_STR + gid;
            const uint32_t* Wl0 = smL + OFF_WDLO + (kc * 8 + tig) * WD_STR + gid;
#pragma unroll
            for (int p = 0; p < 2; p++) {
                if (p < pcnt) {
                    int off = (pstart + p) * 8;
                    uint32_t b0h = Wh0[off], b1h = Wh0[off + 4 * WD_STR];
                    uint32_t b0l = Wl0[off], b1l = Wl0[off + 4 * WD_STR];
                    mma_f16(pacH[p], ah0, ah1, ah2, ah3, b0h, b1h);
                    mma_f16(pacL[p], ah0, ah1, ah2, ah3, b0l, b1l);
                    mma_f16(pacL[p], al0, al1, al2, al3, b0h, b1h);
                }
            }
        }
        {
            uint32_t ah0, ah1, al0, al1;
            ldmx2(ah0, ah1, h2hi_b + 192);
            ldmx2(al0, al1, h2lo_b + 192);
            const uint32_t* Wh0 = smL + OFF_WDHI + (48 + tig) * WD_STR + gid;
            const uint32_t* Wl0 = smL + OFF_WDLO + (48 + tig) * WD_STR + gid;
#pragma unroll
            for (int p = 0; p < 2; p++) {
                if (p < pcnt) {
                    int off = (pstart + p) * 8;
                    uint32_t b0h = Wh0[off], b0l = Wl0[off];
                    mma_f16_k8(pacH[p], ah0, ah1, b0h);
                    mma_f16_k8(pacL[p], ah0, ah1, b0l);
                    mma_f16_k8(pacL[p], al0, al1, b0h);
                }
            }
        }
#pragma unroll
        for (int p = 0; p < 2; p++) {
            if (p < pcnt) {
                int c0 = (pstart + p) * 8 + 2 * tig;
                if (c0 <= 98) {
                    float b0 = sbd[c0], b1 = sbd[c0 + 1];
                    float v0 = fmaxf(pacH[p][0] + pacL[p][0] * INVL + b0, 0.f);
                    float v1 = fmaxf(pacH[p][1] + pacL[p][1] * INVL + b1, 0.f);
                    float v2 = fmaxf(pacH[p][2] + pacL[p][2] * INVL + b0, 0.f);
                    float v3 = fmaxf(pacH[p][3] + pacL[p][3] * INVL + b1, 0.f);
                    *(float2*)(out + ((size_t)(r0c + gid) * TSTEPS + (TSTEPS - 1)) * HID + c0)
                        = make_float2(v0, v1);
                    *(float2*)(out + ((size_t)(r0c + gid + 8) * TSTEPS + (TSTEPS - 1)) * HID + c0)
                        = make_float2(v2, v3);
                }
            }
        }
    }
}

// ---------------------------------------------------------------------------
// Launch
// ---------------------------------------------------------------------------
extern "C" void kernel_launch(void* const* d_in, const int* in_sizes, int n_in,
                              void* d_out, int out_size)
{
    const float* x  = (const float*)d_in[0];   // [2048,250,128]
    const float* Wi = (const float*)d_in[1];   // [128,400]
    const float* Wh = (const float*)d_in[2];   // [100,400]
    const float* bh = (const float*)d_in[3];   // [400]
    const float* Wd = (const float*)d_in[4];   // [100,100]
    const float* bd = (const float*)d_in[5];   // [100]
    float* out = (float*)d_out;                // [2048,250,100]

    const int smem1 = (2 * 64 * A_STR + 2 * 64 * B_STR) * 4 + 80 * 4; // 88,384 B
    cudaFuncSetAttribute(gemm_xz_kernel,
                         cudaFuncAttributeMaxDynamicSharedMemorySize, smem1);
    cudaFuncSetAttribute(lstm_kernel,
                         cudaFuncAttributeMaxDynamicSharedMemorySize, SMEM_L_BYTES);

    wi_split_kernel<<<(64 * G4 + 255) / 256, 256>>>(Wi);
    x_split_kernel<<<(int)(((size_t)MTOT * 64 + 255) / 256), 256>>>(x);
    dim3 g1(MTOT / BM, 5);   // 8000 x 5
    gemm_xz_kernel<<<g1, 128, smem1>>>(bh);
    lstm_kernel<<<BATCH / 16, THREADS_L, SMEM_L_BYTES>>>(Wh, Wd, bd, out);
}